// round 4
// baseline (speedup 1.0000x reference)
#include <cuda_runtime.h>
#include <cuda_bf16.h>

// SPA payment: 4 threads per row of x[N,16], FOUR independent row-quarters per
// thread (front-batched loads -> MLP=4). All warp requests contiguous 512B.

__global__ __launch_bounds__(256)
void spa_payment_x4(const float4* __restrict__ x,
                    float4* __restrict__ out,
                    int nquads) {
    int base = blockIdx.x * (blockDim.x * 4) + threadIdx.x;
    int q0 = base;
    int q1 = base + 256;
    int q2 = base + 512;
    int q3 = base + 768;

    int c0 = q0 < nquads ? q0 : (nquads - 1);
    int c1 = q1 < nquads ? q1 : (nquads - 1);
    int c2 = q2 < nquads ? q2 : (nquads - 1);
    int c3 = q3 < nquads ? q3 : (nquads - 1);

    // Front-batched independent loads (4 outstanding LDG.128 per thread)
    float4 fa = __ldcs(x + c0);
    float4 fb = __ldcs(x + c1);
    float4 fc = __ldcs(x + c2);
    float4 fd = __ldcs(x + c3);

    int quarter = threadIdx.x & 3;   // offsets are 0 mod 4 -> same quarter
    int jb = quarter * 4;

    // ---- local top-2 (first-occurrence argmax) per quad ----
#define LOCAL_TOP2(f, m1, m2, arg)                                          \
    float m1 = f.x, m2 = -__FLT_MAX__; int arg = jb;                        \
    if (f.y > m1) { m2 = m1; m1 = f.y; arg = jb + 1; } else { m2 = f.y; }   \
    if (f.z > m1) { m2 = m1; m1 = f.z; arg = jb + 2; } else if (f.z > m2) { m2 = f.z; } \
    if (f.w > m1) { m2 = m1; m1 = f.w; arg = jb + 3; } else if (f.w > m2) { m2 = f.w; }

    LOCAL_TOP2(fa, am1, am2, aarg)
    LOCAL_TOP2(fb, bm1, bm2, barg)
    LOCAL_TOP2(fc, cm1, cm2, carg)
    LOCAL_TOP2(fd, dm1, dm2, darg)
#undef LOCAL_TOP2

    // ---- interleaved 4-lane group merges (ties -> lower global index) ----
#pragma unroll
    for (int ofs = 1; ofs <= 2; ofs <<= 1) {
#define MERGE(m1, m2, arg)                                                  \
        {                                                                   \
            float om1 = __shfl_xor_sync(0xffffffffu, m1, ofs);              \
            float om2 = __shfl_xor_sync(0xffffffffu, m2, ofs);              \
            int   oar = __shfl_xor_sync(0xffffffffu, arg, ofs);             \
            if (om1 > m1 || (om1 == m1 && oar < arg)) {                     \
                m2 = fmaxf(m1, om2); m1 = om1; arg = oar;                   \
            } else {                                                        \
                m2 = fmaxf(om1, m2);                                        \
            }                                                               \
        }
        MERGE(am1, am2, aarg)
        MERGE(bm1, bm2, barg)
        MERGE(cm1, cm2, carg)
        MERGE(dm1, dm2, darg)
#undef MERGE
    }

    // ---- outputs ----
#define EMIT(m1, m2, arg, o)                                                \
    float4 o;                                                               \
    {                                                                       \
        float o1 = fmaxf(m1, 0.0f), o2 = fmaxf(m2, 0.0f);                   \
        o.x = (jb + 0 == arg) ? o2 : o1;                                    \
        o.y = (jb + 1 == arg) ? o2 : o1;                                    \
        o.z = (jb + 2 == arg) ? o2 : o1;                                    \
        o.w = (jb + 3 == arg) ? o2 : o1;                                    \
    }
    EMIT(am1, am2, aarg, oa)
    EMIT(bm1, bm2, barg, ob)
    EMIT(cm1, cm2, carg, oc)
    EMIT(dm1, dm2, darg, od)
#undef EMIT

    if (q0 < nquads) __stcs(out + q0, oa);
    if (q1 < nquads) __stcs(out + q1, ob);
    if (q2 < nquads) __stcs(out + q2, oc);
    if (q3 < nquads) __stcs(out + q3, od);
}

extern "C" void kernel_launch(void* const* d_in, const int* in_sizes, int n_in,
                              void* d_out, int out_size) {
    const float* x = (const float*)d_in[0];
    float* out = (float*)d_out;
    int nquads = in_sizes[0] / 4;

    int block = 256;
    int per_block = block * 4;
    int grid = (nquads + per_block - 1) / per_block;
    spa_payment_x4<<<grid, block>>>((const float4*)x, (float4*)out, nquads);
}

// round 6
// speedup vs baseline: 1.0004x; 1.0004x over previous
#include <cuda_runtime.h>
#include <cuda_bf16.h>

// SPA payment: 4 threads/row, 4 quads/thread. Branch-free top-2 via
// index-packed u32 keys (nonneg fp32 bits order as unsigned; low 4 mantissa
// bits carry (15-j) so equal-value ties pick the smaller global index,
// matching jax.lax.top_k). Value perturbation <= 2^-20 relative.

__device__ __forceinline__ unsigned ukmax(unsigned a, unsigned b) { return a > b ? a : b; }
__device__ __forceinline__ unsigned ukmin(unsigned a, unsigned b) { return a < b ? a : b; }

__global__ __launch_bounds__(256)
void spa_payment_key(const float4* __restrict__ x,
                     float4* __restrict__ out,
                     int nquads) {
    int base = blockIdx.x * (blockDim.x * 4) + threadIdx.x;
    int q0 = base, q1 = base + 256, q2 = base + 512, q3 = base + 768;

    int c0 = q0 < nquads ? q0 : (nquads - 1);
    int c1 = q1 < nquads ? q1 : (nquads - 1);
    int c2 = q2 < nquads ? q2 : (nquads - 1);
    int c3 = q3 < nquads ? q3 : (nquads - 1);

    // Front-batched independent loads (MLP=4 per thread)
    float4 fa = __ldcs(x + c0);
    float4 fb = __ldcs(x + c1);
    float4 fc = __ldcs(x + c2);
    float4 fd = __ldcs(x + c3);

    int quarter = threadIdx.x & 3;
    int jb = quarter * 4;
    unsigned code0 = 15 - jb;            // element t gets code0 - t

    // key = (bits & ~0xF) | (15 - j); larger key = larger value, ties -> lower j
#define KEYS(f, m1, m2)                                                     \
    unsigned m1, m2;                                                        \
    {                                                                       \
        unsigned k0 = (__float_as_uint(f.x) & ~0xFu) | (code0 - 0);         \
        unsigned k1 = (__float_as_uint(f.y) & ~0xFu) | (code0 - 1);         \
        unsigned k2 = (__float_as_uint(f.z) & ~0xFu) | (code0 - 2);         \
        unsigned k3 = (__float_as_uint(f.w) & ~0xFu) | (code0 - 3);         \
        unsigned hi01 = ukmax(k0, k1), lo01 = ukmin(k0, k1);                \
        unsigned hi23 = ukmax(k2, k3), lo23 = ukmin(k2, k3);                \
        m1 = ukmax(hi01, hi23);                                             \
        m2 = ukmax(ukmin(hi01, hi23), ukmax(lo01, lo23));                   \
    }

    KEYS(fa, am1, am2)
    KEYS(fb, bm1, bm2)
    KEYS(fc, cm1, cm2)
    KEYS(fd, dm1, dm2)
#undef KEYS

    // 4-lane group merges, branch-free, 2 shuffles per reduction per step
#pragma unroll
    for (int ofs = 1; ofs <= 2; ofs <<= 1) {
#define MERGE(m1, m2)                                                       \
        {                                                                   \
            unsigned om1 = __shfl_xor_sync(0xffffffffu, m1, ofs);           \
            unsigned om2 = __shfl_xor_sync(0xffffffffu, m2, ofs);           \
            m2 = ukmax(ukmin(m1, om1), ukmax(m2, om2));                     \
            m1 = ukmax(m1, om1);                                            \
        }
        MERGE(am1, am2)
        MERGE(bm1, bm2)
        MERGE(cm1, cm2)
        MERGE(dm1, dm2)
#undef MERGE
    }

#define EMIT(m1, m2, o)                                                     \
    float4 o;                                                               \
    {                                                                       \
        int arg = 15 - (int)(m1 & 0xFu);                                    \
        float o1 = fmaxf(__uint_as_float(m1 & ~0xFu), 0.0f);                \
        float o2 = fmaxf(__uint_as_float(m2 & ~0xFu), 0.0f);                \
        o.x = (jb + 0 == arg) ? o2 : o1;                                    \
        o.y = (jb + 1 == arg) ? o2 : o1;                                    \
        o.z = (jb + 2 == arg) ? o2 : o1;                                    \
        o.w = (jb + 3 == arg) ? o2 : o1;                                    \
    }

    EMIT(am1, am2, oa)
    EMIT(bm1, bm2, ob)
    EMIT(cm1, cm2, oc)
    EMIT(dm1, dm2, od)
#undef EMIT

    if (q0 < nquads) __stcs(out + q0, oa);
    if (q1 < nquads) __stcs(out + q1, ob);
    if (q2 < nquads) __stcs(out + q2, oc);
    if (q3 < nquads) __stcs(out + q3, od);
}

extern "C" void kernel_launch(void* const* d_in, const int* in_sizes, int n_in,
                              void* d_out, int out_size) {
    const float* x = (const float*)d_in[0];
    float* out = (float*)d_out;
    int nquads = in_sizes[0] / 4;

    int block = 256;
    int per_block = block * 4;
    int grid = (nquads + per_block - 1) / per_block;
    spa_payment_key<<<grid, block>>>((const float4*)x, (float4*)out, nquads);
}